// round 14
// baseline (speedup 1.0000x reference)
#include <cuda_runtime.h>
#include <cuda_fp16.h>

// Fixed problem shapes
#define NN   2000                 // nodes per graph
#define EE   32000                // edges (before self loops)
#define ET   (EE + NN)            // 34000 edges incl. self loops
#define GG   32                   // B*D graphs
#define EMBD 32                   // embedding dim
#define HH   4                    // heads
#define HC   128                  // H*C
#define NEG_SLOPE 0.2f
#define GP1  (GG + 1)             // padded graph stride
#define ELLW 64                   // ELL row capacity (P(deg>64) ~ 1e-19)
#define NP   (ELLW / 4)           // 16 pair-blocks of 4 edges
#define TOKB (NN / 8)             // 250 token blocks
#define ELLB ((ET + 1023) / 1024) // 34 ELL-build blocks
#define XTB  ((GG * NN + 1023) / 1024) // 63 transpose blocks

// ---- scratch (device globals: no allocation allowed) ----
__device__ __half2 g_thl2[NN * 64];             // 512 KB per-TOKEN features (half2)
__device__ __align__(16) float g_tas[NN * HH];  // per-token src-logit component
__device__ __align__(16) float g_tad[NN * HH];  // per-token dst-logit component
__device__ int    g_xT[NN * GG];                // tokens transposed: [n][g]
__device__ int    g_cnt[NN];                    // ELL fill counts (zero-init; gat resets)
__device__ int    g_ell[NN * ELLW];             // ELL src lists (by dst)

// exp(v) * 2^-6 via 2^t: deg-5 FMA polynomial + exponent bit insertion.
// The -6 bias rides the FMA (free); guards fp16 products; cancels in acc/ssum.
__device__ __forceinline__ float fast_exp_s(float v) {
    v = fminf(fmaxf(v, -80.f), 80.f);
    float t = fmaf(v, 1.4426950408889634f, -6.0f);
    float n = rintf(t);
    float f = t - n;
    float p = 0.0013333558f;
    p = fmaf(p, f, 0.0096181291f);
    p = fmaf(p, f, 0.0555041087f);
    p = fmaf(p, f, 0.2402265069f);
    p = fmaf(p, f, 0.6931471806f);
    p = fmaf(p, f, 1.0f);
    return p * __int_as_float(((int)n + 127) << 23);
}

__device__ __forceinline__ float pack_h2(float w) {
    __half2 t = __float2half2_rn(w);
    return __uint_as_float(*reinterpret_cast<unsigned int*>(&t));
}

// ------------------------------------------------------------------
// PREP (one kernel, fully parallel):
//   [0, TOKB)         : per-token tables
//   [TOKB, +ELLB)     : ELL build (atomic append per dst)
//   [TOKB+ELLB, +XTB) : token transpose x_T[n][g]
// ------------------------------------------------------------------
__global__ void __launch_bounds__(1024) prep_kernel(
    const int*   __restrict__ x,
    const int*   __restrict__ adj,
    const float* __restrict__ emb,
    const float* __restrict__ lin_w,
    const float* __restrict__ att_src,
    const float* __restrict__ att_dst)
{
    int tid = threadIdx.x;

    if (blockIdx.x < TOKB) {
        int tok = blockIdx.x * 8 + (tid >> 7);
        int t   = tid & 127;
        const float* er = emb + (size_t)tok * EMBD;

        float acc = 0.f;
#pragma unroll
        for (int k = 0; k < EMBD; k++)
            acc = fmaf(__ldg(er + k), __ldg(lin_w + k * HC + t), acc);

        float partner = __shfl_xor_sync(0xffffffffu, acc, 1);
        if ((t & 1) == 0)
            g_thl2[tok * 64 + (t >> 1)] = __floats2half2_rn(acc, partner);

        int lane = t & 31, h = t >> 5;
        float vs = acc * __ldg(att_src + t);
        float vd = acc * __ldg(att_dst + t);
#pragma unroll
        for (int o = 16; o > 0; o >>= 1) {
            vs += __shfl_xor_sync(0xffffffffu, vs, o);
            vd += __shfl_xor_sync(0xffffffffu, vd, o);
        }
        if (lane == 0) {
            g_tas[tok * HH + h] = vs;
            g_tad[tok * HH + h] = vd;
        }
    } else if (blockIdx.x < TOKB + ELLB) {
        int e = (blockIdx.x - TOKB) * 1024 + tid;
        if (e < ET) {
            int src, dst;
            if (e < EE) { src = adj[e]; dst = adj[EE + e]; }
            else        { src = dst = e - EE; }
            int pos = atomicAdd(&g_cnt[dst], 1);
            if (pos < ELLW) g_ell[dst * ELLW + pos] = src;
        }
    } else {
        int idx = (blockIdx.x - TOKB - ELLB) * 1024 + tid;
        if (idx < GG * NN) {
            int g = idx / NN, n = idx - g * NN;
            g_xT[n * GG + g] = x[idx];
        }
    }
}

// ------------------------------------------------------------------
// GAT aggregation. Block = node n, ALL 32 graphs, 1024 threads.
//   Staging: warp = edge, lane = graph. Degrees PADDED to multiple of 8
//            (dummy edges w=0) -> perfectly uniform gather loop.
//            Weights pre-converted to half2; fp32 ssum accumulated here
//            via spread smem atomics (exact denominator, none in gather).
//   Gather:  warp wg = graph; half-warp = edge parity; lane owns 8
//            channels. Per 2 same-parity edges: 1 LDS.128 (packed
//            (off,wh) pairs) + 2 LDG.128 + 8 HFMA2. Flush every 8 edges
//            (fp16 chain length 4, as validated in R13).
//   Epilogue: parity shfl combine (8 values), ssum read from smem.
// smem layout s_tw[arr][p][j][par*2+hb]: stores coalesced, loads broadcast.
// ------------------------------------------------------------------
__global__ void __launch_bounds__(1024, 2) gat_kernel(
    const float* __restrict__ bias,
    float*       __restrict__ out)
{
    __shared__ float4 s_tw[2][NP][GP1][4];   // 67.6 KB
    __shared__ float  s_sum[GG][HH];         // fp32 softmax denominators
    __shared__ float4 s_ad[GG];

    int tid  = threadIdx.x;
    int n    = blockIdx.x;
    int wg   = tid >> 5;                   // gather: graph | staging: edge
    int j    = tid & 31;                   // gather: lane  | staging: graph
    int half = j >> 4;                     // edge parity
    int k    = j & 15;                     // 16B channel-chunk index (8 ch)
    int h    = k >> 2;                     // head

    if (tid < GG) {
        int tok_d = __ldg(g_xT + n * GG + tid);
        s_ad[tid] = *reinterpret_cast<const float4*>(&g_tad[tok_d * HH]);
    }
    if (tid < GG * HH) s_sum[tid >> 2][tid & 3] = 0.f;

    int deg  = min(g_cnt[n], ELLW);        // read BEFORE the barrier
    int degR = (deg + 7) & ~7;             // padded degree (multiple of 8)
    int ebase = n * ELLW;

    const char* basep = reinterpret_cast<const char*>(g_thl2) + k * 16;
    const float4* cur = &s_tw[h >> 1][0][wg][half * 2 + (h & 1)];
    const int strideP = GP1 * 4;           // float4 units per pair-block

    float4 accA = make_float4(0.f, 0.f, 0.f, 0.f);
    float4 accB = make_float4(0.f, 0.f, 0.f, 0.f);
    __syncthreads();                       // s_ad/s_sum ready; deg reads done
    if (tid == 0) g_cnt[n] = 0;            // reset for next graph replay

    // ---- stage ALL degR edges (warp = edge e; pads write zeros) ----
    for (int e = wg; e < degR; e += 32) {
        float offf, f0, f1, f2, f3;
        if (e < deg) {
            int sidx = __ldg(g_ell + ebase + e);         // broadcast/warp
            int tok  = __ldg(g_xT + sidx * GG + j);      // 128B coalesced
            offf = __int_as_float(tok << 8);             // byte offset
            float4 as = *reinterpret_cast<const float4*>(&g_tas[tok * HH]);
            float4 ad = s_ad[j];
            float l0 = as.x + ad.x, l1 = as.y + ad.y;
            float l2 = as.z + ad.z, l3 = as.w + ad.w;
            l0 = l0 > 0.f ? l0 : NEG_SLOPE * l0;
            l1 = l1 > 0.f ? l1 : NEG_SLOPE * l1;
            l2 = l2 > 0.f ? l2 : NEG_SLOPE * l2;
            l3 = l3 > 0.f ? l3 : NEG_SLOPE * l3;
            float w0 = fast_exp_s(l0), w1 = fast_exp_s(l1);
            float w2 = fast_exp_s(l2), w3 = fast_exp_s(l3);
            atomicAdd(&s_sum[j][0], w0);
            atomicAdd(&s_sum[j][1], w1);
            atomicAdd(&s_sum[j][2], w2);
            atomicAdd(&s_sum[j][3], w3);
            f0 = pack_h2(w0); f1 = pack_h2(w1);
            f2 = pack_h2(w2); f3 = pack_h2(w3);
        } else {
            offf = __int_as_float(0);
            f0 = f1 = f2 = f3 = __int_as_float(0);       // half2(0,0)
        }
        int p = e >> 2, par = e & 1, slot = (e >> 1) & 1;
        char* b0 = reinterpret_cast<char*>(&s_tw[0][p][j][par * 2 + 0]) + slot * 8;
        char* b1 = reinterpret_cast<char*>(&s_tw[0][p][j][par * 2 + 1]) + slot * 8;
        char* b2 = reinterpret_cast<char*>(&s_tw[1][p][j][par * 2 + 0]) + slot * 8;
        char* b3 = reinterpret_cast<char*>(&s_tw[1][p][j][par * 2 + 1]) + slot * 8;
        *reinterpret_cast<float2*>(b0) = make_float2(offf, f0);
        *reinterpret_cast<float2*>(b1) = make_float2(offf, f1);
        *reinterpret_cast<float2*>(b2) = make_float2(offf, f2);
        *reinterpret_cast<float2*>(b3) = make_float2(offf, f3);
    }
    __syncthreads();

    // ---- gather: uniform chunks of 8 edges (4 per parity-lane) ----
    const __half2 hz = __float2half2_rn(0.f);
    for (int c = 0; c < degR; c += 8) {
        int p0 = c >> 2;
        float4 A = cur[p0 * strideP];
        float4 B = cur[(p0 + 1) * strideP];
        __half2 h0 = hz, h1 = hz, h2 = hz, h3 = hz;
#pragma unroll
        for (int u = 0; u < 4; u++) {
            float offF = (u == 0) ? A.x : (u == 1) ? A.z : (u == 2) ? B.x : B.z;
            float whF  = (u == 0) ? A.y : (u == 1) ? A.w : (u == 2) ? B.y : B.w;
            int4 r = __ldg(reinterpret_cast<const int4*>(basep + __float_as_int(offF)));
            unsigned uw = __float_as_uint(whF);
            __half2 wh = *reinterpret_cast<__half2*>(&uw);
            const __half2* q = reinterpret_cast<const __half2*>(&r);
            h0 = __hfma2(wh, q[0], h0);
            h1 = __hfma2(wh, q[1], h1);
            h2 = __hfma2(wh, q[2], h2);
            h3 = __hfma2(wh, q[3], h3);
        }
        float2 u2;
        u2 = __half22float2(h0); accA.x += u2.x; accA.y += u2.y;
        u2 = __half22float2(h1); accA.z += u2.x; accA.w += u2.y;
        u2 = __half22float2(h2); accB.x += u2.x; accB.y += u2.y;
        u2 = __half22float2(h3); accB.z += u2.x; accB.w += u2.y;
    }

    // ---- combine edge-parity partials (lanes k <-> k+16) ----
    accA.x += __shfl_xor_sync(0xffffffffu, accA.x, 16);
    accA.y += __shfl_xor_sync(0xffffffffu, accA.y, 16);
    accA.z += __shfl_xor_sync(0xffffffffu, accA.z, 16);
    accA.w += __shfl_xor_sync(0xffffffffu, accA.w, 16);
    accB.x += __shfl_xor_sync(0xffffffffu, accB.x, 16);
    accB.y += __shfl_xor_sync(0xffffffffu, accB.y, 16);
    accB.z += __shfl_xor_sync(0xffffffffu, accB.z, 16);
    accB.w += __shfl_xor_sync(0xffffffffu, accB.w, 16);

    if (half == 0) {
        float inv = __fdividef(1.f, s_sum[wg][h]);   // 2^-6 scale cancels
        const float4* b4 = reinterpret_cast<const float4*>(bias) + k * 2;
        float4 bb0 = __ldg(b4), bb1 = __ldg(b4 + 1);
        float4* orow = reinterpret_cast<float4*>(out + (size_t)(wg * NN + n) * HC) + k * 2;
        orow[0] = make_float4(fmaf(accA.x, inv, bb0.x), fmaf(accA.y, inv, bb0.y),
                              fmaf(accA.z, inv, bb0.z), fmaf(accA.w, inv, bb0.w));
        orow[1] = make_float4(fmaf(accB.x, inv, bb1.x), fmaf(accB.y, inv, bb1.y),
                              fmaf(accB.z, inv, bb1.z), fmaf(accB.w, inv, bb1.w));
    }
}

// ------------------------------------------------------------------
extern "C" void kernel_launch(void* const* d_in, const int* in_sizes, int n_in,
                              void* d_out, int out_size)
{
    const int*   x       = (const int*)  d_in[0];
    const int*   adj     = (const int*)  d_in[1];
    const float* emb     = (const float*)d_in[2];
    const float* lin_w   = (const float*)d_in[3];
    const float* att_src = (const float*)d_in[4];
    const float* att_dst = (const float*)d_in[5];
    const float* bias    = (const float*)d_in[6];
    float* out = (float*)d_out;

    prep_kernel<<<TOKB + ELLB + XTB, 1024>>>(x, adj, emb, lin_w, att_src, att_dst);
    gat_kernel <<<NN, 1024>>>(bias, out);
}

// round 15
// speedup vs baseline: 1.4031x; 1.4031x over previous
#include <cuda_runtime.h>
#include <cuda_fp16.h>

// Fixed problem shapes
#define NN   2000                 // nodes per graph
#define EE   32000                // edges (before self loops)
#define ET   (EE + NN)            // 34000 edges incl. self loops
#define GG   32                   // B*D graphs
#define EMBD 32                   // embedding dim
#define HH   4                    // heads
#define HC   128                  // H*C
#define NEG_SLOPE 0.2f
#define GP1  (GG + 1)             // padded graph stride
#define ELLW 64                   // ELL row capacity (P(deg>64) ~ 1e-19)
#define ELLP (ELLW + 2)           // staged capacity incl. even-padding
#define TOKB (NN / 8)             // 250 token blocks
#define ELLB ((ET + 1023) / 1024) // 34 ELL-build blocks
#define XTB  ((GG * NN + 1023) / 1024) // 63 transpose blocks

// ---- scratch (device globals: no allocation allowed) ----
__device__ __half2 g_thl2[NN * 64];             // 512 KB per-TOKEN features (half2)
__device__ __align__(16) float g_tas[NN * HH];  // per-token src-logit component
__device__ __align__(16) float g_tad[NN * HH];  // per-token dst-logit component
__device__ int    g_xT[NN * GG];                // tokens transposed: [n][g]
__device__ int    g_cnt[NN];                    // ELL fill counts (zero-init; gat resets)
__device__ int    g_ell[NN * ELLW];             // ELL src lists (by dst)

// exp(v) * 2^-6 via 2^t: deg-5 FMA polynomial + exponent bit insertion.
// The -6 bias rides the FMA (free); guards fp16 products/sums; cancels in acc/ssum.
__device__ __forceinline__ float fast_exp_s(float v) {
    v = fminf(fmaxf(v, -80.f), 80.f);
    float t = fmaf(v, 1.4426950408889634f, -6.0f);
    float n = rintf(t);
    float f = t - n;
    float p = 0.0013333558f;
    p = fmaf(p, f, 0.0096181291f);
    p = fmaf(p, f, 0.0555041087f);
    p = fmaf(p, f, 0.2402265069f);
    p = fmaf(p, f, 0.6931471806f);
    p = fmaf(p, f, 1.0f);
    return p * __int_as_float(((int)n + 127) << 23);
}

// ------------------------------------------------------------------
// PREP (one kernel, fully parallel):
//   [0, TOKB)         : per-token tables
//   [TOKB, +ELLB)     : ELL build (atomic append per dst)
//   [TOKB+ELLB, +XTB) : token transpose x_T[n][g]
// ------------------------------------------------------------------
__global__ void __launch_bounds__(1024) prep_kernel(
    const int*   __restrict__ x,
    const int*   __restrict__ adj,
    const float* __restrict__ emb,
    const float* __restrict__ lin_w,
    const float* __restrict__ att_src,
    const float* __restrict__ att_dst)
{
    int tid = threadIdx.x;

    if (blockIdx.x < TOKB) {
        // ---------------- token tables: 8 tokens per block ----------------
        int tok = blockIdx.x * 8 + (tid >> 7);
        int t   = tid & 127;              // output channel 0..127
        const float* er = emb + (size_t)tok * EMBD;

        float acc = 0.f;
#pragma unroll
        for (int k = 0; k < EMBD; k++)
            acc = fmaf(__ldg(er + k), __ldg(lin_w + k * HC + t), acc);

        float partner = __shfl_xor_sync(0xffffffffu, acc, 1);
        if ((t & 1) == 0)
            g_thl2[tok * 64 + (t >> 1)] = __floats2half2_rn(acc, partner);

        int lane = t & 31, h = t >> 5;
        float vs = acc * __ldg(att_src + t);
        float vd = acc * __ldg(att_dst + t);
#pragma unroll
        for (int o = 16; o > 0; o >>= 1) {
            vs += __shfl_xor_sync(0xffffffffu, vs, o);
            vd += __shfl_xor_sync(0xffffffffu, vd, o);
        }
        if (lane == 0) {
            g_tas[tok * HH + h] = vs;
            g_tad[tok * HH + h] = vd;
        }
    } else if (blockIdx.x < TOKB + ELLB) {
        // ---------------- ELL build (atomic append, bounds-guarded) -------
        int e = (blockIdx.x - TOKB) * 1024 + tid;
        if (e < ET) {
            int src, dst;
            if (e < EE) { src = adj[e]; dst = adj[EE + e]; }
            else        { src = dst = e - EE; }
            int pos = atomicAdd(&g_cnt[dst], 1);
            if (pos < ELLW) g_ell[dst * ELLW + pos] = src;
        }
    } else {
        // ---------------- token transpose: x_T[n][g] = x[g][n] ------------
        int idx = (blockIdx.x - TOKB - ELLB) * 1024 + tid;
        if (idx < GG * NN) {
            int g = idx / NN, n = idx - g * NN;
            g_xT[n * GG + g] = x[idx];
        }
    }
}

// ------------------------------------------------------------------
// GAT aggregation. Block = node n, ALL 32 graphs, 1024 threads.
//   Staging: ALL edges staged once (warp = edge, lane = graph; x_T ->
//            one coalesced 128B token line per edge), degree padded to
//            EVEN with one zero-weight dummy -> gather has no odd/parity
//            special cases. Layout identical to the proven R13 kernel
//            (conflict-free STS.128 / LDS.64 broadcast).
//   Gather:  warp wg = graph; half-warp = edge parity; lane owns 8
//            channels via LDG.128. HALF2 accumulation (HFMA2, scaled
//            weights), flushed to fp32 every 16 edges (chain length 8;
//            two sequential quads bound in-flight LDGs at 4).
//   Epilogue: parity partials combined with shfl_xor(16).
// ------------------------------------------------------------------
__global__ void __launch_bounds__(1024, 2) gat_kernel(
    const float* __restrict__ bias,
    float*       __restrict__ out)
{
    __shared__ float4 s_tw01[ELLP][GP1];   // (off, w0, off, w1)
    __shared__ float4 s_tw23[ELLP][GP1];   // (off, w2, off, w3)
    __shared__ float4 s_ad[GG];

    int tid  = threadIdx.x;
    int n    = blockIdx.x;
    int wg   = tid >> 5;                   // gather: graph | staging: edge
    int j    = tid & 31;                   // gather: lane  | staging: graph
    int half = j >> 4;                     // edge parity
    int k    = j & 15;                     // int4 channel index (8 ch)
    int h    = k >> 2;                     // head

    if (tid < GG) {
        int tok_d = __ldg(g_xT + n * GG + tid);
        s_ad[tid] = *reinterpret_cast<const float4*>(&g_tad[tok_d * HH]);
    }

    int deg  = min(g_cnt[n], ELLW);        // read BEFORE the barrier
    int degR = (deg + 1) & ~1;             // even-padded degree
    int ebase = n * ELLW;

    const char* basep = reinterpret_cast<const char*>(g_thl2) + k * 16;
    const float2* sp = reinterpret_cast<const float2*>(h < 2 ? &s_tw01[0][0]
                                                             : &s_tw23[0][0])
                     + wg * 2 + (h & 1) + half * (GP1 * 2);

    float4 accA = make_float4(0.f, 0.f, 0.f, 0.f);
    float4 accB = make_float4(0.f, 0.f, 0.f, 0.f);
    float  ssum = 0.f;
    __syncthreads();                       // s_ad ready; all deg reads done
    if (tid == 0) g_cnt[n] = 0;            // reset for next graph replay

    // ---- stage ALL degR edges once (warp = edge e; pad writes zeros) ----
#pragma unroll
    for (int e = wg; e < degR; e += 32) {
        float offf, w0, w1, w2, w3;
        if (e < deg) {
            int sidx = __ldg(g_ell + ebase + e);         // broadcast/warp
            int tok  = __ldg(g_xT + sidx * GG + j);      // 128B coalesced
            offf = __int_as_float(tok << 8);             // byte offset
            float4 as = *reinterpret_cast<const float4*>(&g_tas[tok * HH]);
            float4 ad = s_ad[j];
            float l0 = as.x + ad.x, l1 = as.y + ad.y;
            float l2 = as.z + ad.z, l3 = as.w + ad.w;
            l0 = l0 > 0.f ? l0 : NEG_SLOPE * l0;
            l1 = l1 > 0.f ? l1 : NEG_SLOPE * l1;
            l2 = l2 > 0.f ? l2 : NEG_SLOPE * l2;
            l3 = l3 > 0.f ? l3 : NEG_SLOPE * l3;
            w0 = fast_exp_s(l0); w1 = fast_exp_s(l1);
            w2 = fast_exp_s(l2); w3 = fast_exp_s(l3);
        } else {
            offf = __int_as_float(0);
            w0 = w1 = w2 = w3 = 0.f;
        }
        s_tw01[e][j] = make_float4(offf, w0, offf, w1);
        s_tw23[e][j] = make_float4(offf, w2, offf, w3);
    }
    __syncthreads();

    // ---- gather: half2 accumulation, flush every 16 edges (chain 8) ----
    const __half2 hz = __float2half2_rn(0.f);
    const int strideE = GP1 * 2;           // float2 units per edge row
    int i = 0;

    while (i + 16 <= degR) {               // 8 same-parity edges, 2 quads
        __half2 h0 = hz, h1 = hz, h2 = hz, h3 = hz;
#pragma unroll
        for (int qd = 0; qd < 2; qd++) {
#pragma unroll
            for (int u = 0; u < 4; u++) {
                float2 p = sp[(i + qd * 8 + 2 * u) * strideE];
                int4 r = __ldg(reinterpret_cast<const int4*>(basep + __float_as_int(p.x)));
                ssum += p.y;
                __half2 wh = __float2half2_rn(p.y);
                const __half2* q = reinterpret_cast<const __half2*>(&r);
                h0 = __hfma2(wh, q[0], h0);
                h1 = __hfma2(wh, q[1], h1);
                h2 = __hfma2(wh, q[2], h2);
                h3 = __hfma2(wh, q[3], h3);
            }
        }
        float2 u2;
        u2 = __half22float2(h0); accA.x += u2.x; accA.y += u2.y;
        u2 = __half22float2(h1); accA.z += u2.x; accA.w += u2.y;
        u2 = __half22float2(h2); accB.x += u2.x; accB.y += u2.y;
        u2 = __half22float2(h3); accB.z += u2.x; accB.w += u2.y;
        i += 16;
    }

    {   // remainder: uniform pairs, chain <= 8, no odd-edge case
        __half2 h0 = hz, h1 = hz, h2 = hz, h3 = hz;
        for (; i < degR; i += 2) {
            float2 p = sp[i * strideE];
            int4 r = __ldg(reinterpret_cast<const int4*>(basep + __float_as_int(p.x)));
            ssum += p.y;
            __half2 wh = __float2half2_rn(p.y);
            const __half2* q = reinterpret_cast<const __half2*>(&r);
            h0 = __hfma2(wh, q[0], h0);
            h1 = __hfma2(wh, q[1], h1);
            h2 = __hfma2(wh, q[2], h2);
            h3 = __hfma2(wh, q[3], h3);
        }
        float2 u2;
        u2 = __half22float2(h0); accA.x += u2.x; accA.y += u2.y;
        u2 = __half22float2(h1); accA.z += u2.x; accA.w += u2.y;
        u2 = __half22float2(h2); accB.x += u2.x; accB.y += u2.y;
        u2 = __half22float2(h3); accB.z += u2.x; accB.w += u2.y;
    }

    // ---- combine edge-parity partials (lanes k <-> k+16) ----
    ssum   += __shfl_xor_sync(0xffffffffu, ssum,   16);
    accA.x += __shfl_xor_sync(0xffffffffu, accA.x, 16);
    accA.y += __shfl_xor_sync(0xffffffffu, accA.y, 16);
    accA.z += __shfl_xor_sync(0xffffffffu, accA.z, 16);
    accA.w += __shfl_xor_sync(0xffffffffu, accA.w, 16);
    accB.x += __shfl_xor_sync(0xffffffffu, accB.x, 16);
    accB.y += __shfl_xor_sync(0xffffffffu, accB.y, 16);
    accB.z += __shfl_xor_sync(0xffffffffu, accB.z, 16);
    accB.w += __shfl_xor_sync(0xffffffffu, accB.w, 16);

    if (half == 0) {
        float inv = __fdividef(1.f, ssum);     // 2^-6 scale cancels here
        const float4* b4 = reinterpret_cast<const float4*>(bias) + k * 2;
        float4 bb0 = __ldg(b4), bb1 = __ldg(b4 + 1);
        float4* orow = reinterpret_cast<float4*>(out + (size_t)(wg * NN + n) * HC) + k * 2;
        orow[0] = make_float4(fmaf(accA.x, inv, bb0.x), fmaf(accA.y, inv, bb0.y),
                              fmaf(accA.z, inv, bb0.z), fmaf(accA.w, inv, bb0.w));
        orow[1] = make_float4(fmaf(accB.x, inv, bb1.x), fmaf(accB.y, inv, bb1.y),
                              fmaf(accB.z, inv, bb1.z), fmaf(accB.w, inv, bb1.w));
    }
}

// ------------------------------------------------------------------
extern "C" void kernel_launch(void* const* d_in, const int* in_sizes, int n_in,
                              void* d_out, int out_size)
{
    const int*   x       = (const int*)  d_in[0];
    const int*   adj     = (const int*)  d_in[1];
    const float* emb     = (const float*)d_in[2];
    const float* lin_w   = (const float*)d_in[3];
    const float* att_src = (const float*)d_in[4];
    const float* att_dst = (const float*)d_in[5];
    const float* bias    = (const float*)d_in[6];
    float* out = (float*)d_out;

    prep_kernel<<<TOKB + ELLB + XTB, 1024>>>(x, adj, emb, lin_w, att_src, att_dst);
    gat_kernel <<<NN, 1024>>>(bias, out);
}

// round 16
// speedup vs baseline: 1.4785x; 1.0538x over previous
#include <cuda_runtime.h>
#include <cuda_fp16.h>

// Fixed problem shapes
#define NN   2000                 // nodes per graph
#define EE   32000                // edges (before self loops)
#define ET   (EE + NN)            // 34000 edges incl. self loops
#define GG   32                   // B*D graphs
#define EMBD 32                   // embedding dim
#define HH   4                    // heads
#define HC   128                  // H*C
#define NEG_SLOPE 0.2f
#define GP1  (GG + 1)             // padded graph stride
#define ELLW 64                   // ELL row capacity (P(deg>64) ~ 1e-19)
#define TOKB (NN / 8)             // 250 token blocks
#define ELLB ((ET + 1023) / 1024) // 34 ELL-build blocks
#define XTB  ((GG * NN + 1023) / 1024) // 63 transpose blocks

// ---- scratch (device globals: no allocation allowed) ----
__device__ __half2 g_thl2[NN * 64];             // 512 KB per-TOKEN features (half2)
__device__ __align__(16) float g_tas[NN * HH];  // per-token src-logit component
__device__ __align__(16) float g_tad[NN * HH];  // per-token dst-logit component
__device__ int    g_xT[NN * GG];                // tokens transposed: [n][g]
__device__ int    g_cnt[NN];                    // ELL fill counts (zero-init; gat resets)
__device__ int    g_ell[NN * ELLW];             // ELL src lists (by dst)

// exp(v) * 2^-6 via 2^t: deg-5 FMA polynomial + exponent bit insertion.
// The -6 bias rides the FMA (free); guards fp16 products/sums; cancels in acc/ssum.
__device__ __forceinline__ float fast_exp_s(float v) {
    v = fminf(fmaxf(v, -80.f), 80.f);
    float t = fmaf(v, 1.4426950408889634f, -6.0f);
    float n = rintf(t);
    float f = t - n;
    float p = 0.0013333558f;
    p = fmaf(p, f, 0.0096181291f);
    p = fmaf(p, f, 0.0555041087f);
    p = fmaf(p, f, 0.2402265069f);
    p = fmaf(p, f, 0.6931471806f);
    p = fmaf(p, f, 1.0f);
    return p * __int_as_float(((int)n + 127) << 23);
}

// ------------------------------------------------------------------
// PREP (one kernel, fully parallel):
//   [0, TOKB)         : per-token tables
//   [TOKB, +ELLB)     : ELL build (atomic append per dst)
//   [TOKB+ELLB, +XTB) : token transpose x_T[n][g]
// ------------------------------------------------------------------
__global__ void __launch_bounds__(1024) prep_kernel(
    const int*   __restrict__ x,
    const int*   __restrict__ adj,
    const float* __restrict__ emb,
    const float* __restrict__ lin_w,
    const float* __restrict__ att_src,
    const float* __restrict__ att_dst)
{
    int tid = threadIdx.x;

    if (blockIdx.x < TOKB) {
        // ---------------- token tables: 8 tokens per block ----------------
        int tok = blockIdx.x * 8 + (tid >> 7);
        int t   = tid & 127;              // output channel 0..127
        const float* er = emb + (size_t)tok * EMBD;

        float acc = 0.f;
#pragma unroll
        for (int k = 0; k < EMBD; k++)
            acc = fmaf(__ldg(er + k), __ldg(lin_w + k * HC + t), acc);

        float partner = __shfl_xor_sync(0xffffffffu, acc, 1);
        if ((t & 1) == 0)
            g_thl2[tok * 64 + (t >> 1)] = __floats2half2_rn(acc, partner);

        int lane = t & 31, h = t >> 5;
        float vs = acc * __ldg(att_src + t);
        float vd = acc * __ldg(att_dst + t);
#pragma unroll
        for (int o = 16; o > 0; o >>= 1) {
            vs += __shfl_xor_sync(0xffffffffu, vs, o);
            vd += __shfl_xor_sync(0xffffffffu, vd, o);
        }
        if (lane == 0) {
            g_tas[tok * HH + h] = vs;
            g_tad[tok * HH + h] = vd;
        }
    } else if (blockIdx.x < TOKB + ELLB) {
        // ---------------- ELL build (atomic append, bounds-guarded) -------
        int e = (blockIdx.x - TOKB) * 1024 + tid;
        if (e < ET) {
            int src, dst;
            if (e < EE) { src = adj[e]; dst = adj[EE + e]; }
            else        { src = dst = e - EE; }
            int pos = atomicAdd(&g_cnt[dst], 1);
            if (pos < ELLW) g_ell[dst * ELLW + pos] = src;
        }
    } else {
        // ---------------- token transpose: x_T[n][g] = x[g][n] ------------
        int idx = (blockIdx.x - TOKB - ELLB) * 1024 + tid;
        if (idx < GG * NN) {
            int g = idx / NN, n = idx - g * NN;
            g_xT[n * GG + g] = x[idx];
        }
    }
}

// ------------------------------------------------------------------
// GAT aggregation. Block = node n, ALL 32 graphs, 1024 threads.
// Identical to the measured-best R13 kernel EXCEPT: softmax denominators
// are accumulated during STAGING via conflict-free smem atomics
// (s_sum, stride 5), removing the ssum FADD chain from the gather loop
// and the ssum shfl from the epilogue. Denominator is exact fp32.
//   Staging: warp = edge, lane = graph; x_T -> one coalesced 128B token
//            line per edge. ONE barrier.
//   Gather:  warp wg = graph; half-warp = edge parity; lane owns 8
//            channels via LDG.128. half2 accumulation (HFMA2, scaled
//            weights), flushed to fp32 every 8 edges (chain 4).
//   Epilogue: parity partials combined with shfl_xor(16).
// ------------------------------------------------------------------
__global__ void __launch_bounds__(1024, 2) gat_kernel(
    const float* __restrict__ bias,
    float*       __restrict__ out)
{
    __shared__ float4 s_tw01[ELLW][GP1];   // (off, w0, off, w1)
    __shared__ float4 s_tw23[ELLW][GP1];   // (off, w2, off, w3)
    __shared__ float4 s_ad[GG];
    __shared__ float  s_sum[GG * 5];       // stride-5: conflict-free atomics

    int tid  = threadIdx.x;
    int n    = blockIdx.x;
    int wg   = tid >> 5;                   // gather: graph | staging: edge
    int j    = tid & 31;                   // gather: lane  | staging: graph
    int half = j >> 4;                     // edge parity
    int k    = j & 15;                     // int4 channel index (8 ch)
    int h    = k >> 2;                     // head

    if (tid < GG) {
        int tok_d = __ldg(g_xT + n * GG + tid);
        s_ad[tid] = *reinterpret_cast<const float4*>(&g_tad[tok_d * HH]);
    }
    if (tid < GG * 5) s_sum[tid] = 0.f;

    int deg = min(g_cnt[n], ELLW);         // read BEFORE the barrier
    int ebase = n * ELLW;

    const char* basep = reinterpret_cast<const char*>(g_thl2) + k * 16;
    const float2* sp = reinterpret_cast<const float2*>(h < 2 ? &s_tw01[0][0]
                                                             : &s_tw23[0][0])
                     + wg * 2 + (h & 1) + half * (GP1 * 2);

    float4 accA = make_float4(0.f, 0.f, 0.f, 0.f);
    float4 accB = make_float4(0.f, 0.f, 0.f, 0.f);
    __syncthreads();                       // s_ad/s_sum ready; deg reads done
    if (tid == 0) g_cnt[n] = 0;            // reset for next graph replay

    // ---- stage ALL edges once: warp = edge e (e = wg, wg+32) ----
#pragma unroll
    for (int e = wg; e < deg; e += 32) {
        int sidx = __ldg(g_ell + ebase + e);             // broadcast/warp
        int tok  = __ldg(g_xT + sidx * GG + j);          // 128B coalesced
        float offf = __int_as_float(tok << 8);           // byte offset
        float4 as = *reinterpret_cast<const float4*>(&g_tas[tok * HH]);
        float4 ad = s_ad[j];
        float l0 = as.x + ad.x, l1 = as.y + ad.y;
        float l2 = as.z + ad.z, l3 = as.w + ad.w;
        l0 = l0 > 0.f ? l0 : NEG_SLOPE * l0;
        l1 = l1 > 0.f ? l1 : NEG_SLOPE * l1;
        l2 = l2 > 0.f ? l2 : NEG_SLOPE * l2;
        l3 = l3 > 0.f ? l3 : NEG_SLOPE * l3;
        float w0 = fast_exp_s(l0), w1 = fast_exp_s(l1);
        float w2 = fast_exp_s(l2), w3 = fast_exp_s(l3);
        atomicAdd(&s_sum[j * 5 + 0], w0);
        atomicAdd(&s_sum[j * 5 + 1], w1);
        atomicAdd(&s_sum[j * 5 + 2], w2);
        atomicAdd(&s_sum[j * 5 + 3], w3);
        s_tw01[e][j] = make_float4(offf, w0, offf, w1);
        s_tw23[e][j] = make_float4(offf, w2, offf, w3);
    }
    __syncthreads();

    // ---- gather: half2 accumulation, flush every 8-edge chunk ----
    const __half2 hz = __float2half2_rn(0.f);
    int i = 0;

    while (i + 8 <= deg) {                 // full chunk: 4 pairs, no branches
        __half2 h0 = hz, h1 = hz, h2 = hz, h3 = hz;
#pragma unroll
        for (int u = 0; u < 4; u++) {
            float2 p = sp[(i + 2 * u) * (GP1 * 2)];
            int4 r = __ldg(reinterpret_cast<const int4*>(basep + __float_as_int(p.x)));
            __half2 wh = __float2half2_rn(p.y);
            const __half2* q = reinterpret_cast<const __half2*>(&r);
            h0 = __hfma2(wh, q[0], h0);
            h1 = __hfma2(wh, q[1], h1);
            h2 = __hfma2(wh, q[2], h2);
            h3 = __hfma2(wh, q[3], h3);
        }
        float2 u2;
        u2 = __half22float2(h0); accA.x += u2.x; accA.y += u2.y;
        u2 = __half22float2(h1); accA.z += u2.x; accA.w += u2.y;
        u2 = __half22float2(h2); accB.x += u2.x; accB.y += u2.y;
        u2 = __half22float2(h3); accB.z += u2.x; accB.w += u2.y;
        i += 8;
    }

    {   // remainder: <4 pairs + possible odd edge (chain still <= 4)
        __half2 h0 = hz, h1 = hz, h2 = hz, h3 = hz;
        for (; i + 2 <= deg; i += 2) {
            float2 p = sp[i * (GP1 * 2)];
            int4 r = __ldg(reinterpret_cast<const int4*>(basep + __float_as_int(p.x)));
            __half2 wh = __float2half2_rn(p.y);
            const __half2* q = reinterpret_cast<const __half2*>(&r);
            h0 = __hfma2(wh, q[0], h0);
            h1 = __hfma2(wh, q[1], h1);
            h2 = __hfma2(wh, q[2], h2);
            h3 = __hfma2(wh, q[3], h3);
        }
        if (i < deg && half == 0) {        // odd final edge: lanes 0-15 only
            float2 p = sp[i * (GP1 * 2)];
            int4 r = __ldg(reinterpret_cast<const int4*>(basep + __float_as_int(p.x)));
            __half2 wh = __float2half2_rn(p.y);
            const __half2* q = reinterpret_cast<const __half2*>(&r);
            h0 = __hfma2(wh, q[0], h0);
            h1 = __hfma2(wh, q[1], h1);
            h2 = __hfma2(wh, q[2], h2);
            h3 = __hfma2(wh, q[3], h3);
        }
        float2 u2;
        u2 = __half22float2(h0); accA.x += u2.x; accA.y += u2.y;
        u2 = __half22float2(h1); accA.z += u2.x; accA.w += u2.y;
        u2 = __half22float2(h2); accB.x += u2.x; accB.y += u2.y;
        u2 = __half22float2(h3); accB.z += u2.x; accB.w += u2.y;
    }

    // ---- combine edge-parity partials (lanes k <-> k+16) ----
    accA.x += __shfl_xor_sync(0xffffffffu, accA.x, 16);
    accA.y += __shfl_xor_sync(0xffffffffu, accA.y, 16);
    accA.z += __shfl_xor_sync(0xffffffffu, accA.z, 16);
    accA.w += __shfl_xor_sync(0xffffffffu, accA.w, 16);
    accB.x += __shfl_xor_sync(0xffffffffu, accB.x, 16);
    accB.y += __shfl_xor_sync(0xffffffffu, accB.y, 16);
    accB.z += __shfl_xor_sync(0xffffffffu, accB.z, 16);
    accB.w += __shfl_xor_sync(0xffffffffu, accB.w, 16);

    if (half == 0) {
        float inv = __fdividef(1.f, s_sum[wg * 5 + h]);  // 2^-6 scale cancels
        const float4* b4 = reinterpret_cast<const float4*>(bias) + k * 2;
        float4 bb0 = __ldg(b4), bb1 = __ldg(b4 + 1);
        float4* orow = reinterpret_cast<float4*>(out + (size_t)(wg * NN + n) * HC) + k * 2;
        orow[0] = make_float4(fmaf(accA.x, inv, bb0.x), fmaf(accA.y, inv, bb0.y),
                              fmaf(accA.z, inv, bb0.z), fmaf(accA.w, inv, bb0.w));
        orow[1] = make_float4(fmaf(accB.x, inv, bb1.x), fmaf(accB.y, inv, bb1.y),
                              fmaf(accB.z, inv, bb1.z), fmaf(accB.w, inv, bb1.w));
    }
}

// ------------------------------------------------------------------
extern "C" void kernel_launch(void* const* d_in, const int* in_sizes, int n_in,
                              void* d_out, int out_size)
{
    const int*   x       = (const int*)  d_in[0];
    const int*   adj     = (const int*)  d_in[1];
    const float* emb     = (const float*)d_in[2];
    const float* lin_w   = (const float*)d_in[3];
    const float* att_src = (const float*)d_in[4];
    const float* att_dst = (const float*)d_in[5];
    const float* bias    = (const float*)d_in[6];
    float* out = (float*)d_out;

    prep_kernel<<<TOKB + ELLB + XTB, 1024>>>(x, adj, emb, lin_w, att_src, att_dst);
    gat_kernel <<<NN, 1024>>>(bias, out);
}